// round 1
// baseline (speedup 1.0000x reference)
#include <cuda_runtime.h>
#include <cstdint>
#include <math.h>

// Problem constants
#define NUM_TOK 8192
#define DIM     1024
#define NEXP    8
#define FFN     4096

// GEMM tiling
#define BM 128
#define BN 128
#define BK 32
#define MAX_SLOTS (2*NUM_TOK + NEXP*BM)   // 17408 (128-aligned regions worst case)
#define MAX_MTILES (MAX_SLOTS/BM)         // 136

// ---------------- device scratch (static, allocation-free) ----------------
__device__ int   g_counts[NEXP];
__device__ int   g_fill[NEXP];
__device__ int   g_off[NEXP+1];
__device__ int   g_tok_e[2*NUM_TOK];
__device__ float g_tok_w[2*NUM_TOK];
__device__ int   g_slot_tok[MAX_SLOTS];
__device__ float g_slot_w[MAX_SLOTS];
__device__ float g_h[(size_t)MAX_SLOTS * FFN];   // ~285 MB intermediate

// ---------------- helpers ----------------
__device__ __forceinline__ float tf32r(float x) {
    uint32_t u;
    asm("cvt.rna.tf32.f32 %0, %1;" : "=r"(u) : "f"(x));
    return __uint_as_float(u);
}

__device__ __forceinline__ void mma_tf32(float c[4], const uint32_t a[4], const uint32_t b[2]) {
    asm volatile(
        "mma.sync.aligned.m16n8k8.row.col.f32.tf32.tf32.f32 "
        "{%0,%1,%2,%3},{%4,%5,%6,%7},{%8,%9},{%0,%1,%2,%3};"
        : "+f"(c[0]), "+f"(c[1]), "+f"(c[2]), "+f"(c[3])
        : "r"(a[0]), "r"(a[1]), "r"(a[2]), "r"(a[3]), "r"(b[0]), "r"(b[1]));
}

__device__ __forceinline__ float gelu_exact(float v) {
    return 0.5f * v * (1.0f + erff(v * 0.70710678118654752f));
}

// ---------------- kernels ----------------

// Zero output + per-launch counters (out is poisoned by harness).
__global__ void init_kernel(float* __restrict__ out, int n) {
    int i = blockIdx.x * blockDim.x + threadIdx.x;
    if (i < n) out[i] = 0.0f;
    if (i < NEXP) { g_counts[i] = 0; g_fill[i] = 0; }
}

// One warp per token: scores = x . router_w[e], top-2, softmax, count experts.
__global__ void router_kernel(const float* __restrict__ x, const float* __restrict__ rw) {
    int warp = threadIdx.x >> 5, lane = threadIdx.x & 31;
    int t = blockIdx.x * 8 + warp;
    float acc[NEXP];
#pragma unroll
    for (int e = 0; e < NEXP; e++) acc[e] = 0.0f;
    const float* xp = x + (size_t)t * DIM;
    for (int k = lane; k < DIM; k += 32) {
        float xv = xp[k];
#pragma unroll
        for (int e = 0; e < NEXP; e++) acc[e] += xv * rw[e * DIM + k];
    }
#pragma unroll
    for (int e = 0; e < NEXP; e++) {
#pragma unroll
        for (int o = 16; o > 0; o >>= 1) acc[e] += __shfl_xor_sync(0xffffffffu, acc[e], o);
    }
    if (lane == 0) {
        int be = 0; float bv = acc[0];
#pragma unroll
        for (int e = 1; e < NEXP; e++) if (acc[e] > bv) { bv = acc[e]; be = e; }
        int be2 = -1; float bv2 = -1e30f;
#pragma unroll
        for (int e = 0; e < NEXP; e++) if (e != be && acc[e] > bv2) { bv2 = acc[e]; be2 = e; }
        float p0 = 1.0f / (1.0f + expf(bv2 - bv));   // softmax over {bv, bv2}
        g_tok_e[2 * t] = be;  g_tok_e[2 * t + 1] = be2;
        g_tok_w[2 * t] = p0;  g_tok_w[2 * t + 1] = 1.0f - p0;
        atomicAdd(&g_counts[be], 1);
        atomicAdd(&g_counts[be2], 1);
    }
}

// 128-aligned per-expert offsets + mark padding slots (token = -1).
__global__ void offsets_kernel() {
    if (threadIdx.x == 0) {
        int o = 0;
        for (int e = 0; e < NEXP; e++) {
            g_off[e] = o;
            o += ((g_counts[e] + BM - 1) / BM) * BM;
        }
        g_off[NEXP] = o;
    }
    __syncthreads();
    for (int i = threadIdx.x; i < NEXP * BM; i += blockDim.x) {
        int e = i / BM, j = i % BM;
        int idx = g_off[e] + g_counts[e] + j;
        if (idx < g_off[e + 1]) { g_slot_tok[idx] = -1; g_slot_w[idx] = 0.0f; }
    }
}

// Compact (token, expert) pairs into per-expert contiguous slot ranges.
__global__ void place_kernel() {
    int t = blockIdx.x * blockDim.x + threadIdx.x;
    if (t >= NUM_TOK) return;
#pragma unroll
    for (int k = 0; k < 2; k++) {
        int e = g_tok_e[2 * t + k];
        int p = atomicAdd(&g_fill[e], 1);
        int idx = g_off[e] + p;
        g_slot_tok[idx] = t;
        g_slot_w[idx] = g_tok_w[2 * t + k];
    }
}

// GEMM1: h[slot][f] = gelu( x[token] . W1[e][f] ), tf32 mma, 128x128x32 tiles.
__global__ void __launch_bounds__(256)
gemm1_kernel(const float* __restrict__ x, const float* __restrict__ w1) {
    int m0 = blockIdx.x * BM;
    if (m0 >= g_off[NEXP]) return;
    int e = 0;
    while (m0 >= g_off[e + 1]) e++;
    const float* w1e = w1 + (size_t)e * FFN * DIM;
    int n0 = blockIdx.y * BN;

    __shared__ float As[BM][BK + 4];     // stride 36: conflict-free frag loads
    __shared__ float Bs[BK][BN + 8];     // stride 136
    __shared__ int   stok[BM];

    int tid = threadIdx.x;
    if (tid < BM) stok[tid] = g_slot_tok[m0 + tid];
    __syncthreads();

    int warp = tid >> 5, lane = tid & 31;
    int wm = (warp >> 2) * 64, wn = (warp & 3) * 32;
    int g = lane >> 2, tg = lane & 3;

    float c[4][4][4];
#pragma unroll
    for (int i = 0; i < 4; i++)
#pragma unroll
        for (int j = 0; j < 4; j++)
#pragma unroll
            for (int k = 0; k < 4; k++) c[i][j][k] = 0.0f;

    for (int k0 = 0; k0 < DIM; k0 += BK) {
        // load A tile (gathered token rows, zero for padding slots)
#pragma unroll
        for (int i = 0; i < 4; i++) {
            int idx = tid + i * 256;
            int m = idx >> 3, kk = (idx & 7) * 4;
            int tok = stok[m];
            float4 v = make_float4(0.f, 0.f, 0.f, 0.f);
            if (tok >= 0) v = *(const float4*)(x + (size_t)tok * DIM + k0 + kk);
            As[m][kk]     = tf32r(v.x);
            As[m][kk + 1] = tf32r(v.y);
            As[m][kk + 2] = tf32r(v.z);
            As[m][kk + 3] = tf32r(v.w);
        }
        // load B tile transposed: Bs[k][n] = W1[e][n0+n][k0+k]
#pragma unroll
        for (int i = 0; i < 4; i++) {
            int idx = tid + i * 256;
            int n = idx & 127, kq = (idx >> 7) * 4;
            float4 v = *(const float4*)(w1e + (size_t)(n0 + n) * DIM + k0 + kq);
            Bs[kq][n]     = tf32r(v.x);
            Bs[kq + 1][n] = tf32r(v.y);
            Bs[kq + 2][n] = tf32r(v.z);
            Bs[kq + 3][n] = tf32r(v.w);
        }
        __syncthreads();
#pragma unroll
        for (int ks = 0; ks < BK; ks += 8) {
            uint32_t a[4][4], b[4][2];
#pragma unroll
            for (int mt = 0; mt < 4; mt++) {
                int mb = wm + mt * 16;
                a[mt][0] = __float_as_uint(As[mb + g][ks + tg]);
                a[mt][1] = __float_as_uint(As[mb + g + 8][ks + tg]);
                a[mt][2] = __float_as_uint(As[mb + g][ks + tg + 4]);
                a[mt][3] = __float_as_uint(As[mb + g + 8][ks + tg + 4]);
            }
#pragma unroll
            for (int nt = 0; nt < 4; nt++) {
                int nb = wn + nt * 8;
                b[nt][0] = __float_as_uint(Bs[ks + tg][nb + g]);
                b[nt][1] = __float_as_uint(Bs[ks + tg + 4][nb + g]);
            }
#pragma unroll
            for (int mt = 0; mt < 4; mt++)
#pragma unroll
                for (int nt = 0; nt < 4; nt++)
                    mma_tf32(c[mt][nt], a[mt], b[nt]);
        }
        __syncthreads();
    }

    // epilogue: exact gelu, store h
#pragma unroll
    for (int mt = 0; mt < 4; mt++) {
#pragma unroll
        for (int nt = 0; nt < 4; nt++) {
            int mb = m0 + wm + mt * 16 + g;
            int nb = n0 + wn + nt * 8 + tg * 2;
            size_t o0 = (size_t)mb * FFN + nb;
            size_t o1 = (size_t)(mb + 8) * FFN + nb;
            g_h[o0]     = gelu_exact(c[mt][nt][0]);
            g_h[o0 + 1] = gelu_exact(c[mt][nt][1]);
            g_h[o1]     = gelu_exact(c[mt][nt][2]);
            g_h[o1 + 1] = gelu_exact(c[mt][nt][3]);
        }
    }
}

// GEMM2: out[token][d] += w_slot * ( h[slot] . W2[e][d] )
__global__ void __launch_bounds__(256)
gemm2_kernel(const float* __restrict__ w2, float* __restrict__ out) {
    int m0 = blockIdx.x * BM;
    if (m0 >= g_off[NEXP]) return;
    int e = 0;
    while (m0 >= g_off[e + 1]) e++;
    const float* w2e = w2 + (size_t)e * DIM * FFN;
    int n0 = blockIdx.y * BN;

    __shared__ float As[BM][BK + 4];
    __shared__ float Bs[BK][BN + 8];
    __shared__ int   stok[BM];
    __shared__ float sw[BM];

    int tid = threadIdx.x;
    if (tid < BM) { stok[tid] = g_slot_tok[m0 + tid]; sw[tid] = g_slot_w[m0 + tid]; }
    __syncthreads();

    int warp = tid >> 5, lane = tid & 31;
    int wm = (warp >> 2) * 64, wn = (warp & 3) * 32;
    int g = lane >> 2, tg = lane & 3;

    float c[4][4][4];
#pragma unroll
    for (int i = 0; i < 4; i++)
#pragma unroll
        for (int j = 0; j < 4; j++)
#pragma unroll
            for (int k = 0; k < 4; k++) c[i][j][k] = 0.0f;

    for (int k0 = 0; k0 < FFN; k0 += BK) {
#pragma unroll
        for (int i = 0; i < 4; i++) {
            int idx = tid + i * 256;
            int m = idx >> 3, kk = (idx & 7) * 4;
            float4 v = *(const float4*)(g_h + (size_t)(m0 + m) * FFN + k0 + kk);
            As[m][kk]     = tf32r(v.x);
            As[m][kk + 1] = tf32r(v.y);
            As[m][kk + 2] = tf32r(v.z);
            As[m][kk + 3] = tf32r(v.w);
        }
#pragma unroll
        for (int i = 0; i < 4; i++) {
            int idx = tid + i * 256;
            int n = idx & 127, kq = (idx >> 7) * 4;
            float4 v = *(const float4*)(w2e + (size_t)(n0 + n) * FFN + k0 + kq);
            Bs[kq][n]     = tf32r(v.x);
            Bs[kq + 1][n] = tf32r(v.y);
            Bs[kq + 2][n] = tf32r(v.z);
            Bs[kq + 3][n] = tf32r(v.w);
        }
        __syncthreads();
#pragma unroll
        for (int ks = 0; ks < BK; ks += 8) {
            uint32_t a[4][4], b[4][2];
#pragma unroll
            for (int mt = 0; mt < 4; mt++) {
                int mb = wm + mt * 16;
                a[mt][0] = __float_as_uint(As[mb + g][ks + tg]);
                a[mt][1] = __float_as_uint(As[mb + g + 8][ks + tg]);
                a[mt][2] = __float_as_uint(As[mb + g][ks + tg + 4]);
                a[mt][3] = __float_as_uint(As[mb + g + 8][ks + tg + 4]);
            }
#pragma unroll
            for (int nt = 0; nt < 4; nt++) {
                int nb = wn + nt * 8;
                b[nt][0] = __float_as_uint(Bs[ks + tg][nb + g]);
                b[nt][1] = __float_as_uint(Bs[ks + tg + 4][nb + g]);
            }
#pragma unroll
            for (int mt = 0; mt < 4; mt++)
#pragma unroll
                for (int nt = 0; nt < 4; nt++)
                    mma_tf32(c[mt][nt], a[mt], b[nt]);
        }
        __syncthreads();
    }

    // epilogue: scale by routing weight, scatter-add into out
#pragma unroll
    for (int mt = 0; mt < 4; mt++) {
        int ml0 = wm + mt * 16 + g;
        int ml1 = ml0 + 8;
        int tok0 = stok[ml0], tok1 = stok[ml1];
        float w0 = sw[ml0], w1v = sw[ml1];
#pragma unroll
        for (int nt = 0; nt < 4; nt++) {
            int nb = n0 + wn + nt * 8 + tg * 2;
            if (tok0 >= 0) {
                atomicAdd(out + (size_t)tok0 * DIM + nb,     c[mt][nt][0] * w0);
                atomicAdd(out + (size_t)tok0 * DIM + nb + 1, c[mt][nt][1] * w0);
            }
            if (tok1 >= 0) {
                atomicAdd(out + (size_t)tok1 * DIM + nb,     c[mt][nt][2] * w1v);
                atomicAdd(out + (size_t)tok1 * DIM + nb + 1, c[mt][nt][3] * w1v);
            }
        }
    }
}

// ---------------- launcher ----------------
extern "C" void kernel_launch(void* const* d_in, const int* in_sizes, int n_in,
                              void* d_out, int out_size) {
    const float* x  = (const float*)d_in[0];
    const float* rw = (const float*)d_in[1];
    const float* w1 = (const float*)d_in[2];
    const float* w2 = (const float*)d_in[3];
    float* out = (float*)d_out;

    init_kernel<<<(out_size + 255) / 256, 256>>>(out, out_size);
    router_kernel<<<NUM_TOK / 8, 256>>>(x, rw);
    offsets_kernel<<<1, 256>>>();
    place_kernel<<<NUM_TOK / 256, 256>>>();
    gemm1_kernel<<<dim3(MAX_MTILES, FFN / BN), 256>>>(x, w1);
    gemm2_kernel<<<dim3(MAX_MTILES, DIM / BN), 256>>>(w2, out);
}

// round 3
// speedup vs baseline: 1.7770x; 1.7770x over previous
#include <cuda_runtime.h>
#include <cstdint>
#include <math.h>

// Problem constants
#define NUM_TOK 8192
#define DIM     1024
#define NEXP    8
#define FFN     4096

// GEMM tiling
#define BM 128
#define BN 128
#define BK 32                               // floats per k-tile = 128 B/row
#define NSTAGE 3
#define MAX_SLOTS (2*NUM_TOK + NEXP*BM)     // 17408
#define MAX_MTILES (MAX_SLOTS/BM)           // 136

#define TILE_BYTES 16384                    // 128 rows x 128 B
#define STAGE_BYTES (2*TILE_BYTES)          // A + B
#define SMEM_TOTAL (NSTAGE*STAGE_BYTES + 128)

// ---------------- device scratch (static, allocation-free) ----------------
__device__ int   g_counts[NEXP];
__device__ int   g_fill[NEXP];
__device__ int   g_off[NEXP+1];
__device__ int   g_tok_e[2*NUM_TOK];
__device__ float g_tok_w[2*NUM_TOK];
__device__ int   g_slot_tok[MAX_SLOTS];
__device__ float g_slot_w[MAX_SLOTS];
__device__ float g_h[(size_t)MAX_SLOTS * FFN];   // ~285 MB intermediate

// ---------------- helpers ----------------
__device__ __forceinline__ float gelu_exact(float v) {
    return 0.5f * v * (1.0f + erff(v * 0.70710678118654752f));
}
__device__ __forceinline__ uint32_t smem_u32(const void* p) {
    uint32_t a;
    asm("{ .reg .u64 t; cvta.to.shared.u64 t, %1; cvt.u32.u64 %0, t; }" : "=r"(a) : "l"(p));
    return a;
}
__device__ __forceinline__ void mma_tf32(float c[4], const uint32_t a[4], const uint32_t b[2]) {
    asm volatile(
        "mma.sync.aligned.m16n8k8.row.col.f32.tf32.tf32.f32 "
        "{%0,%1,%2,%3},{%4,%5,%6,%7},{%8,%9},{%0,%1,%2,%3};"
        : "+f"(c[0]), "+f"(c[1]), "+f"(c[2]), "+f"(c[3])
        : "r"(a[0]), "r"(a[1]), "r"(a[2]), "r"(a[3]), "r"(b[0]), "r"(b[1]));
}
__device__ __forceinline__ void cpa16(uint32_t dst, const void* src, int srcbytes) {
    asm volatile("cp.async.cg.shared.global [%0], [%1], 16, %2;"
                 :: "r"(dst), "l"(src), "r"(srcbytes) : "memory");
}
__device__ __forceinline__ void cpa_commit() { asm volatile("cp.async.commit_group;" ::: "memory"); }
__device__ __forceinline__ void cpa_wait()   { asm volatile("cp.async.wait_group %0;" :: "n"(NSTAGE-1) : "memory"); }
__device__ __forceinline__ uint32_t lds32(uint32_t addr) {
    uint32_t v;
    asm volatile("ld.shared.b32 %0, [%1];" : "=r"(v) : "r"(addr));
    return v;
}

// ---------------- small kernels ----------------
__global__ void init_kernel(float* __restrict__ out, int n) {
    int i = blockIdx.x * blockDim.x + threadIdx.x;
    if (i < n) out[i] = 0.0f;
    if (i < NEXP) { g_counts[i] = 0; g_fill[i] = 0; }
}

__global__ void router_kernel(const float* __restrict__ x, const float* __restrict__ rw) {
    int warp = threadIdx.x >> 5, lane = threadIdx.x & 31;
    int t = blockIdx.x * 8 + warp;
    float acc[NEXP];
#pragma unroll
    for (int e = 0; e < NEXP; e++) acc[e] = 0.0f;
    const float* xp = x + (size_t)t * DIM;
    for (int k = lane; k < DIM; k += 32) {
        float xv = xp[k];
#pragma unroll
        for (int e = 0; e < NEXP; e++) acc[e] += xv * rw[e * DIM + k];
    }
#pragma unroll
    for (int e = 0; e < NEXP; e++) {
#pragma unroll
        for (int o = 16; o > 0; o >>= 1) acc[e] += __shfl_xor_sync(0xffffffffu, acc[e], o);
    }
    if (lane == 0) {
        int be = 0; float bv = acc[0];
#pragma unroll
        for (int e = 1; e < NEXP; e++) if (acc[e] > bv) { bv = acc[e]; be = e; }
        int be2 = -1; float bv2 = -1e30f;
#pragma unroll
        for (int e = 0; e < NEXP; e++) if (e != be && acc[e] > bv2) { bv2 = acc[e]; be2 = e; }
        float p0 = 1.0f / (1.0f + expf(bv2 - bv));
        g_tok_e[2 * t] = be;  g_tok_e[2 * t + 1] = be2;
        g_tok_w[2 * t] = p0;  g_tok_w[2 * t + 1] = 1.0f - p0;
        atomicAdd(&g_counts[be], 1);
        atomicAdd(&g_counts[be2], 1);
    }
}

__global__ void offsets_kernel() {
    if (threadIdx.x == 0) {
        int o = 0;
        for (int e = 0; e < NEXP; e++) {
            g_off[e] = o;
            o += ((g_counts[e] + BM - 1) / BM) * BM;
        }
        g_off[NEXP] = o;
    }
    __syncthreads();
    for (int i = threadIdx.x; i < NEXP * BM; i += blockDim.x) {
        int e = i / BM, j = i % BM;
        int idx = g_off[e] + g_counts[e] + j;
        if (idx < g_off[e + 1]) { g_slot_tok[idx] = -1; g_slot_w[idx] = 0.0f; }
    }
}

__global__ void place_kernel() {
    int t = blockIdx.x * blockDim.x + threadIdx.x;
    if (t >= NUM_TOK) return;
#pragma unroll
    for (int k = 0; k < 2; k++) {
        int e = g_tok_e[2 * t + k];
        int p = atomicAdd(&g_fill[e], 1);
        int idx = g_off[e] + p;
        g_slot_tok[idx] = t;
        g_slot_w[idx] = g_tok_w[2 * t + k];
    }
}

// ================= pipelined tf32 GEMM core =================
// Both tiles stored as 128 rows x 128 B, chunk-swizzled: chunk' = ch ^ (row&7).
// Fragment rows always have (row & 7) == g, so xor term = (chunk ^ g) << 4.

struct FragCtx {
    uint32_t aB, bB;      // stage-0 tile bases (smem addr)
    int wm, wn, g, tg;
};

__device__ __forceinline__ void compute_tile(const FragCtx& f, int s, float c[4][4][4]) {
    uint32_t aB = f.aB + s * STAGE_BYTES;
    uint32_t bB = f.bB + s * STAGE_BYTES;
#pragma unroll
    for (int ks8 = 0; ks8 < 4; ks8++) {
        uint32_t xo = ((uint32_t)((ks8 * 2) ^ f.g)) << 4;
        uint32_t a[4][4], b[4][2];
#pragma unroll
        for (int mt = 0; mt < 4; mt++) {
            uint32_t r0 = aB + (uint32_t)(f.wm + mt * 16 + f.g) * 128 + f.tg * 4 + xo;
            a[mt][0] = lds32(r0)        + 0x1000u;
            a[mt][1] = lds32(r0 + 1024) + 0x1000u;
            a[mt][2] = lds32(r0 ^ 16)   + 0x1000u;
            a[mt][3] = lds32((r0 + 1024) ^ 16) + 0x1000u;
        }
#pragma unroll
        for (int nt = 0; nt < 4; nt++) {
            uint32_t rn = bB + (uint32_t)(f.wn + nt * 8 + f.g) * 128 + f.tg * 4 + xo;
            b[nt][0] = lds32(rn)      + 0x1000u;
            b[nt][1] = lds32(rn ^ 16) + 0x1000u;
        }
#pragma unroll
        for (int mt = 0; mt < 4; mt++)
#pragma unroll
            for (int nt = 0; nt < 4; nt++)
                mma_tf32(c[mt][nt], a[mt], b[nt]);
    }
}

// ---------------- GEMM1: h = gelu(x_gather @ W1^T) ----------------
__global__ void __launch_bounds__(256, 2)
gemm1_p(const float* __restrict__ x, const float* __restrict__ w1) {
    extern __shared__ char smem[];
    __shared__ int stok[BM];

    const int tid = threadIdx.x;
    const int m0 = blockIdx.x * BM;
    if (m0 >= g_off[NEXP]) return;
    int e = 0;
    while (m0 >= g_off[e + 1]) e++;
    const float* w1e = w1 + (size_t)e * FFN * DIM;
    const int n0 = blockIdx.y * BN;

    if (tid < BM) stok[tid] = g_slot_tok[m0 + tid];
    __syncthreads();

    uint32_t sb = (smem_u32(smem) + 127u) & ~127u;

    // per-thread load slots: 4 x (row, chunk)
    const float* asrc[4]; const float* bsrc[4];
    uint32_t dsto[4]; int asz[4];
#pragma unroll
    for (int i = 0; i < 4; i++) {
        int idx = tid + i * 256;
        int row = idx >> 3, ch = idx & 7;
        int tok = stok[row];
        asz[i]  = (tok < 0) ? 0 : 16;
        asrc[i] = x + (size_t)((tok < 0) ? 0 : tok) * DIM + ch * 4;
        bsrc[i] = w1e + (size_t)(n0 + row) * DIM + ch * 4;
        dsto[i] = (uint32_t)row * 128 + ((uint32_t)(ch ^ (row & 7)) << 4);
    }

    FragCtx f;
    f.aB = sb; f.bB = sb + TILE_BYTES;
    int warp = tid >> 5, lane = tid & 31;
    f.wm = (warp >> 2) * 64; f.wn = (warp & 3) * 32;
    f.g = lane >> 2; f.tg = lane & 3;

    float c[4][4][4];
#pragma unroll
    for (int i = 0; i < 4; i++)
#pragma unroll
        for (int j = 0; j < 4; j++)
#pragma unroll
            for (int k = 0; k < 4; k++) c[i][j][k] = 0.0f;

    const int NK = DIM / BK;   // 32
#pragma unroll
    for (int s = 0; s < NSTAGE; s++) {
        uint32_t ab = sb + s * STAGE_BYTES, bb = ab + TILE_BYTES;
#pragma unroll
        for (int i = 0; i < 4; i++) {
            cpa16(ab + dsto[i], asrc[i], asz[i]);
            cpa16(bb + dsto[i], bsrc[i], 16);
            asrc[i] += BK; bsrc[i] += BK;
        }
        cpa_commit();
    }

    for (int kt = 0; kt < NK; kt++) {
        int s = kt % NSTAGE;
        cpa_wait();
        __syncthreads();
        compute_tile(f, s, c);
        __syncthreads();
        if (kt + NSTAGE < NK) {
            uint32_t ab = sb + s * STAGE_BYTES, bb = ab + TILE_BYTES;
#pragma unroll
            for (int i = 0; i < 4; i++) {
                cpa16(ab + dsto[i], asrc[i], asz[i]);
                cpa16(bb + dsto[i], bsrc[i], 16);
                asrc[i] += BK; bsrc[i] += BK;
            }
        }
        cpa_commit();   // keep group count in lockstep even on tail iters
    }

    // epilogue: gelu + store h (fp32)
    int g = f.g, tg = f.tg;
#pragma unroll
    for (int mt = 0; mt < 4; mt++) {
#pragma unroll
        for (int nt = 0; nt < 4; nt++) {
            int mb = m0 + f.wm + mt * 16 + g;
            int nb = n0 + f.wn + nt * 8 + tg * 2;
            size_t o0 = (size_t)mb * FFN + nb;
            size_t o1 = (size_t)(mb + 8) * FFN + nb;
            g_h[o0]     = gelu_exact(c[mt][nt][0]);
            g_h[o0 + 1] = gelu_exact(c[mt][nt][1]);
            g_h[o1]     = gelu_exact(c[mt][nt][2]);
            g_h[o1 + 1] = gelu_exact(c[mt][nt][3]);
        }
    }
}

// ---------------- GEMM2: out += w_slot * (h @ W2^T) ----------------
__global__ void __launch_bounds__(256, 2)
gemm2_p(const float* __restrict__ w2, float* __restrict__ out) {
    extern __shared__ char smem[];
    __shared__ int   stok[BM];
    __shared__ float swv[BM];

    const int tid = threadIdx.x;
    const int m0 = blockIdx.x * BM;
    if (m0 >= g_off[NEXP]) return;
    int e = 0;
    while (m0 >= g_off[e + 1]) e++;
    const float* w2e = w2 + (size_t)e * DIM * FFN;
    const int n0 = blockIdx.y * BN;

    if (tid < BM) { stok[tid] = g_slot_tok[m0 + tid]; swv[tid] = g_slot_w[m0 + tid]; }
    __syncthreads();

    uint32_t sb = (smem_u32(smem) + 127u) & ~127u;

    const float* asrc[4]; const float* bsrc[4];
    uint32_t dsto[4];
#pragma unroll
    for (int i = 0; i < 4; i++) {
        int idx = tid + i * 256;
        int row = idx >> 3, ch = idx & 7;
        asrc[i] = g_h + (size_t)(m0 + row) * FFN + ch * 4;
        bsrc[i] = w2e + (size_t)(n0 + row) * FFN + ch * 4;
        dsto[i] = (uint32_t)row * 128 + ((uint32_t)(ch ^ (row & 7)) << 4);
    }

    FragCtx f;
    f.aB = sb; f.bB = sb + TILE_BYTES;
    int warp = tid >> 5, lane = tid & 31;
    f.wm = (warp >> 2) * 64; f.wn = (warp & 3) * 32;
    f.g = lane >> 2; f.tg = lane & 3;

    float c[4][4][4];
#pragma unroll
    for (int i = 0; i < 4; i++)
#pragma unroll
        for (int j = 0; j < 4; j++)
#pragma unroll
            for (int k = 0; k < 4; k++) c[i][j][k] = 0.0f;

    const int NK = FFN / BK;   // 128
#pragma unroll
    for (int s = 0; s < NSTAGE; s++) {
        uint32_t ab = sb + s * STAGE_BYTES, bb = ab + TILE_BYTES;
#pragma unroll
        for (int i = 0; i < 4; i++) {
            cpa16(ab + dsto[i], asrc[i], 16);
            cpa16(bb + dsto[i], bsrc[i], 16);
            asrc[i] += BK; bsrc[i] += BK;
        }
        cpa_commit();
    }

    for (int kt = 0; kt < NK; kt++) {
        int s = kt % NSTAGE;
        cpa_wait();
        __syncthreads();
        compute_tile(f, s, c);
        __syncthreads();
        if (kt + NSTAGE < NK) {
            uint32_t ab = sb + s * STAGE_BYTES, bb = ab + TILE_BYTES;
#pragma unroll
            for (int i = 0; i < 4; i++) {
                cpa16(ab + dsto[i], asrc[i], 16);
                cpa16(bb + dsto[i], bsrc[i], 16);
                asrc[i] += BK; bsrc[i] += BK;
            }
        }
        cpa_commit();
    }

    // epilogue: scale + atomic scatter
    int g = f.g, tg = f.tg;
#pragma unroll
    for (int mt = 0; mt < 4; mt++) {
        int ml0 = f.wm + mt * 16 + g;
        int ml1 = ml0 + 8;
        int tok0 = stok[ml0], tok1 = stok[ml1];
        float w0 = swv[ml0], w1v = swv[ml1];
#pragma unroll
        for (int nt = 0; nt < 4; nt++) {
            int nb = n0 + f.wn + nt * 8 + tg * 2;
            if (tok0 >= 0) {
                atomicAdd(out + (size_t)tok0 * DIM + nb,     c[mt][nt][0] * w0);
                atomicAdd(out + (size_t)tok0 * DIM + nb + 1, c[mt][nt][1] * w0);
            }
            if (tok1 >= 0) {
                atomicAdd(out + (size_t)tok1 * DIM + nb,     c[mt][nt][2] * w1v);
                atomicAdd(out + (size_t)tok1 * DIM + nb + 1, c[mt][nt][3] * w1v);
            }
        }
    }
}

// ---------------- launcher ----------------
extern "C" void kernel_launch(void* const* d_in, const int* in_sizes, int n_in,
                              void* d_out, int out_size) {
    const float* x  = (const float*)d_in[0];
    const float* rw = (const float*)d_in[1];
    const float* w1 = (const float*)d_in[2];
    const float* w2 = (const float*)d_in[3];
    float* out = (float*)d_out;

    static int configured = 0;
    if (!configured) {
        cudaFuncSetAttribute(gemm1_p, cudaFuncAttributeMaxDynamicSharedMemorySize, SMEM_TOTAL);
        cudaFuncSetAttribute(gemm2_p, cudaFuncAttributeMaxDynamicSharedMemorySize, SMEM_TOTAL);
        configured = 1;
    }

    init_kernel<<<(out_size + 255) / 256, 256>>>(out, out_size);
    router_kernel<<<NUM_TOK / 8, 256>>>(x, rw);
    offsets_kernel<<<1, 256>>>();
    place_kernel<<<NUM_TOK / 256, 256>>>();
    gemm1_p<<<dim3(MAX_MTILES, FFN / BN), 256, SMEM_TOTAL>>>(x, w1);
    gemm2_p<<<dim3(MAX_MTILES, DIM / BN), 256, SMEM_TOTAL>>>(w2, out);
}

// round 4
// speedup vs baseline: 3.5759x; 2.0123x over previous
#include <cuda_runtime.h>
#include <cuda_fp16.h>
#include <cstdint>
#include <math.h>

// Problem constants
#define NUM_TOK 8192
#define DIM     1024
#define NEXP    8
#define FFN     4096

// GEMM tiling (fp16): 128x128 tiles, K-tile = 64 halves = 128 B/row
#define BM 128
#define BN 128
#define BKF 64
#define NSTAGE 3
#define MAX_SLOTS (2*NUM_TOK + NEXP*BM)     // 17408
#define MAX_MTILES (MAX_SLOTS/BM)           // 136

#define TILE_BYTES 16384                    // 128 rows x 128 B
#define STAGE_BYTES (2*TILE_BYTES)
#define SMEM_TOTAL (NSTAGE*STAGE_BYTES + 128)

// ---------------- device scratch ----------------
__device__ int    g_counts[NEXP];
__device__ int    g_fill[NEXP];
__device__ int    g_off[NEXP+1];
__device__ int    g_tok_e[2*NUM_TOK];
__device__ float  g_tok_w[2*NUM_TOK];
__device__ int    g_slot_tok[MAX_SLOTS];
__device__ float  g_slot_w[MAX_SLOTS];
__device__ __half g_xh[(size_t)NUM_TOK * DIM];        // 16.8 MB
__device__ __half g_w1h[(size_t)NEXP * FFN * DIM];    // 67 MB
__device__ __half g_w2h[(size_t)NEXP * DIM * FFN];    // 67 MB
__device__ __half g_hh[(size_t)MAX_SLOTS * FFN];      // 142 MB

// ---------------- helpers ----------------
__device__ __forceinline__ float gelu_exact(float v) {
    return 0.5f * v * (1.0f + erff(v * 0.70710678118654752f));
}
__device__ __forceinline__ uint32_t smem_u32(const void* p) {
    uint32_t a;
    asm("{ .reg .u64 t; cvta.to.shared.u64 t, %1; cvt.u32.u64 %0, t; }" : "=r"(a) : "l"(p));
    return a;
}
__device__ __forceinline__ void mma_f16(float c[4], const uint32_t a[4], const uint32_t b[2]) {
    asm volatile(
        "mma.sync.aligned.m16n8k16.row.col.f32.f16.f16.f32 "
        "{%0,%1,%2,%3},{%4,%5,%6,%7},{%8,%9},{%0,%1,%2,%3};"
        : "+f"(c[0]), "+f"(c[1]), "+f"(c[2]), "+f"(c[3])
        : "r"(a[0]), "r"(a[1]), "r"(a[2]), "r"(a[3]), "r"(b[0]), "r"(b[1]));
}
__device__ __forceinline__ void ldsm4(uint32_t& r0, uint32_t& r1, uint32_t& r2, uint32_t& r3,
                                      uint32_t addr) {
    asm volatile("ldmatrix.sync.aligned.m8n8.x4.shared.b16 {%0,%1,%2,%3}, [%4];"
                 : "=r"(r0), "=r"(r1), "=r"(r2), "=r"(r3) : "r"(addr));
}
__device__ __forceinline__ void cpa16(uint32_t dst, const void* src, int srcbytes) {
    asm volatile("cp.async.cg.shared.global [%0], [%1], 16, %2;"
                 :: "r"(dst), "l"(src), "r"(srcbytes) : "memory");
}
__device__ __forceinline__ void cpa_commit() { asm volatile("cp.async.commit_group;" ::: "memory"); }
__device__ __forceinline__ void cpa_wait()   { asm volatile("cp.async.wait_group %0;" :: "n"(NSTAGE-1) : "memory"); }

// ---------------- small kernels ----------------
__global__ void init_kernel(float* __restrict__ out, int n) {
    int i = blockIdx.x * blockDim.x + threadIdx.x;
    if (i < n) out[i] = 0.0f;
    if (i < NEXP) { g_counts[i] = 0; g_fill[i] = 0; }
}

// fp32 -> fp16 (RN) streaming conversion; which: 0=x, 1=w1, 2=w2
__global__ void f2h_kernel(const float4* __restrict__ src, int which, int n8) {
    __half* dst = (which == 0) ? g_xh : (which == 1) ? g_w1h : g_w2h;
    int i = blockIdx.x * blockDim.x + threadIdx.x;
    if (i >= n8) return;
    float4 v0 = src[2 * i], v1 = src[2 * i + 1];
    __half2 h0 = __floats2half2_rn(v0.x, v0.y);
    __half2 h1 = __floats2half2_rn(v0.z, v0.w);
    __half2 h2 = __floats2half2_rn(v1.x, v1.y);
    __half2 h3 = __floats2half2_rn(v1.z, v1.w);
    uint4 o;
    o.x = *(uint32_t*)&h0; o.y = *(uint32_t*)&h1;
    o.z = *(uint32_t*)&h2; o.w = *(uint32_t*)&h3;
    ((uint4*)dst)[i] = o;
}

__global__ void router_kernel(const float* __restrict__ x, const float* __restrict__ rw) {
    int warp = threadIdx.x >> 5, lane = threadIdx.x & 31;
    int t = blockIdx.x * 8 + warp;
    float acc[NEXP];
#pragma unroll
    for (int e = 0; e < NEXP; e++) acc[e] = 0.0f;
    const float* xp = x + (size_t)t * DIM;
    for (int k = lane; k < DIM; k += 32) {
        float xv = xp[k];
#pragma unroll
        for (int e = 0; e < NEXP; e++) acc[e] += xv * rw[e * DIM + k];
    }
#pragma unroll
    for (int e = 0; e < NEXP; e++) {
#pragma unroll
        for (int o = 16; o > 0; o >>= 1) acc[e] += __shfl_xor_sync(0xffffffffu, acc[e], o);
    }
    if (lane == 0) {
        int be = 0; float bv = acc[0];
#pragma unroll
        for (int e = 1; e < NEXP; e++) if (acc[e] > bv) { bv = acc[e]; be = e; }
        int be2 = -1; float bv2 = -1e30f;
#pragma unroll
        for (int e = 0; e < NEXP; e++) if (e != be && acc[e] > bv2) { bv2 = acc[e]; be2 = e; }
        float p0 = 1.0f / (1.0f + expf(bv2 - bv));
        g_tok_e[2 * t] = be;  g_tok_e[2 * t + 1] = be2;
        g_tok_w[2 * t] = p0;  g_tok_w[2 * t + 1] = 1.0f - p0;
        atomicAdd(&g_counts[be], 1);
        atomicAdd(&g_counts[be2], 1);
    }
}

__global__ void offsets_kernel() {
    if (threadIdx.x == 0) {
        int o = 0;
        for (int e = 0; e < NEXP; e++) {
            g_off[e] = o;
            o += ((g_counts[e] + BM - 1) / BM) * BM;
        }
        g_off[NEXP] = o;
    }
    __syncthreads();
    for (int i = threadIdx.x; i < NEXP * BM; i += blockDim.x) {
        int e = i / BM, j = i % BM;
        int idx = g_off[e] + g_counts[e] + j;
        if (idx < g_off[e + 1]) { g_slot_tok[idx] = -1; g_slot_w[idx] = 0.0f; }
    }
}

__global__ void place_kernel() {
    int t = blockIdx.x * blockDim.x + threadIdx.x;
    if (t >= NUM_TOK) return;
#pragma unroll
    for (int k = 0; k < 2; k++) {
        int e = g_tok_e[2 * t + k];
        int p = atomicAdd(&g_fill[e], 1);
        int idx = g_off[e] + p;
        g_slot_tok[idx] = t;
        g_slot_w[idx] = g_tok_w[2 * t + k];
    }
}

// ================= fp16 pipelined GEMM core =================
// Tiles: 128 rows x 128 B (64 halves), chunk-swizzled: ch' = ch ^ (row & 7).
// Fragments via ldmatrix.x4; mma m16n8k16 fp16 -> fp32.

struct Frag {
    uint32_t aB, bB;          // stage-0 tile bases
    int wm, wn;               // warp tile origin (64 x 32)
    int rlA, selA, rlA7;      // A ldmatrix lane row / chunk-half / row&7
    int nlB, selB, nlB7;      // B ldmatrix lane row / chunk-half / row&7
    int g, tg;                // epilogue indices
};

__device__ __forceinline__ void frag_init(Frag& f, uint32_t sb, int tid) {
    f.aB = sb; f.bB = sb + TILE_BYTES;
    int warp = tid >> 5, lane = tid & 31;
    f.wm = (warp >> 2) * 64; f.wn = (warp & 3) * 32;
    f.rlA = lane & 15;  f.selA = lane >> 4;        f.rlA7 = f.rlA & 7;
    f.nlB = ((lane >> 4) << 3) + (lane & 7);
    f.selB = (lane >> 3) & 1;                      f.nlB7 = f.nlB & 7;
    f.g = lane >> 2; f.tg = lane & 3;
}

__device__ __forceinline__ void compute_tile(const Frag& f, int s, float c[4][4][4]) {
    uint32_t aS = f.aB + s * STAGE_BYTES;
    uint32_t bS = f.bB + s * STAGE_BYTES;
#pragma unroll
    for (int ks = 0; ks < 4; ks++) {          // 4 x k16 steps = k64
        uint32_t a[4][4], b[4][2];
        uint32_t offA = ((uint32_t)((ks * 2 + f.selA) ^ f.rlA7)) << 4;
#pragma unroll
        for (int mt = 0; mt < 4; mt++) {
            uint32_t ad = aS + (uint32_t)(f.wm + mt * 16 + f.rlA) * 128 + offA;
            ldsm4(a[mt][0], a[mt][1], a[mt][2], a[mt][3], ad);
        }
        uint32_t offB = ((uint32_t)((ks * 2 + f.selB) ^ f.nlB7)) << 4;
#pragma unroll
        for (int p = 0; p < 2; p++) {
            uint32_t bd = bS + (uint32_t)(f.wn + p * 16 + f.nlB) * 128 + offB;
            ldsm4(b[2*p][0], b[2*p][1], b[2*p+1][0], b[2*p+1][1], bd);
        }
#pragma unroll
        for (int mt = 0; mt < 4; mt++)
#pragma unroll
            for (int nt = 0; nt < 4; nt++)
                mma_f16(c[mt][nt], a[mt], b[nt]);
    }
}

// ---------------- GEMM1: h = gelu(x_gather @ W1^T), fp16 in, fp16 out ----------------
__global__ void __launch_bounds__(256, 2)
gemm1_p() {
    extern __shared__ char smem[];
    __shared__ int stok[BM];

    const int tid = threadIdx.x;
    const int m0 = blockIdx.x * BM;
    if (m0 >= g_off[NEXP]) return;
    int e = 0;
    while (m0 >= g_off[e + 1]) e++;
    const __half* w1e = g_w1h + (size_t)e * FFN * DIM;
    const int n0 = blockIdx.y * BN;

    if (tid < BM) stok[tid] = g_slot_tok[m0 + tid];
    __syncthreads();

    uint32_t sb = (smem_u32(smem) + 127u) & ~127u;

    const __half* asrc[4]; const __half* bsrc[4];
    uint32_t dsto[4]; int asz[4];
#pragma unroll
    for (int i = 0; i < 4; i++) {
        int idx = tid + i * 256;
        int row = idx >> 3, ch = idx & 7;
        int tok = stok[row];
        asz[i]  = (tok < 0) ? 0 : 16;
        asrc[i] = g_xh + (size_t)((tok < 0) ? 0 : tok) * DIM + ch * 8;
        bsrc[i] = w1e + (size_t)(n0 + row) * DIM + ch * 8;
        dsto[i] = (uint32_t)row * 128 + ((uint32_t)(ch ^ (row & 7)) << 4);
    }

    Frag f; frag_init(f, sb, tid);

    float c[4][4][4];
#pragma unroll
    for (int i = 0; i < 4; i++)
#pragma unroll
        for (int j = 0; j < 4; j++)
#pragma unroll
            for (int k = 0; k < 4; k++) c[i][j][k] = 0.0f;

    const int NK = DIM / BKF;   // 16
#pragma unroll
    for (int s = 0; s < NSTAGE; s++) {
        uint32_t ab = sb + s * STAGE_BYTES, bb = ab + TILE_BYTES;
#pragma unroll
        for (int i = 0; i < 4; i++) {
            cpa16(ab + dsto[i], asrc[i], asz[i]);
            cpa16(bb + dsto[i], bsrc[i], 16);
            asrc[i] += BKF; bsrc[i] += BKF;
        }
        cpa_commit();
    }

    for (int kt = 0; kt < NK; kt++) {
        int s = kt % NSTAGE;
        cpa_wait();
        __syncthreads();
        compute_tile(f, s, c);
        __syncthreads();
        if (kt + NSTAGE < NK) {
            uint32_t ab = sb + s * STAGE_BYTES, bb = ab + TILE_BYTES;
#pragma unroll
            for (int i = 0; i < 4; i++) {
                cpa16(ab + dsto[i], asrc[i], asz[i]);
                cpa16(bb + dsto[i], bsrc[i], 16);
                asrc[i] += BKF; bsrc[i] += BKF;
            }
        }
        cpa_commit();
    }

    // epilogue: gelu -> fp16 h
#pragma unroll
    for (int mt = 0; mt < 4; mt++) {
#pragma unroll
        for (int nt = 0; nt < 4; nt++) {
            int mb = m0 + f.wm + mt * 16 + f.g;
            int nb = n0 + f.wn + nt * 8 + f.tg * 2;
            __half2 v0 = __floats2half2_rn(gelu_exact(c[mt][nt][0]), gelu_exact(c[mt][nt][1]));
            __half2 v1 = __floats2half2_rn(gelu_exact(c[mt][nt][2]), gelu_exact(c[mt][nt][3]));
            *(__half2*)(g_hh + (size_t)mb * FFN + nb) = v0;
            *(__half2*)(g_hh + (size_t)(mb + 8) * FFN + nb) = v1;
        }
    }
}

// ---------------- GEMM2: out += w_slot * (h @ W2^T) ----------------
__global__ void __launch_bounds__(256, 2)
gemm2_p(float* __restrict__ out) {
    extern __shared__ char smem[];
    __shared__ int   stok[BM];
    __shared__ float swv[BM];

    const int tid = threadIdx.x;
    const int m0 = blockIdx.x * BM;
    if (m0 >= g_off[NEXP]) return;
    int e = 0;
    while (m0 >= g_off[e + 1]) e++;
    const __half* w2e = g_w2h + (size_t)e * DIM * FFN;
    const int n0 = blockIdx.y * BN;

    if (tid < BM) { stok[tid] = g_slot_tok[m0 + tid]; swv[tid] = g_slot_w[m0 + tid]; }
    __syncthreads();

    uint32_t sb = (smem_u32(smem) + 127u) & ~127u;

    const __half* asrc[4]; const __half* bsrc[4];
    uint32_t dsto[4];
#pragma unroll
    for (int i = 0; i < 4; i++) {
        int idx = tid + i * 256;
        int row = idx >> 3, ch = idx & 7;
        asrc[i] = g_hh + (size_t)(m0 + row) * FFN + ch * 8;
        bsrc[i] = w2e + (size_t)(n0 + row) * FFN + ch * 8;
        dsto[i] = (uint32_t)row * 128 + ((uint32_t)(ch ^ (row & 7)) << 4);
    }

    Frag f; frag_init(f, sb, tid);

    float c[4][4][4];
#pragma unroll
    for (int i = 0; i < 4; i++)
#pragma unroll
        for (int j = 0; j < 4; j++)
#pragma unroll
            for (int k = 0; k < 4; k++) c[i][j][k] = 0.0f;

    const int NK = FFN / BKF;   // 64
#pragma unroll
    for (int s = 0; s < NSTAGE; s++) {
        uint32_t ab = sb + s * STAGE_BYTES, bb = ab + TILE_BYTES;
#pragma unroll
        for (int i = 0; i < 4; i++) {
            cpa16(ab + dsto[i], asrc[i], 16);
            cpa16(bb + dsto[i], bsrc[i], 16);
            asrc[i] += BKF; bsrc[i] += BKF;
        }
        cpa_commit();
    }

    for (int kt = 0; kt < NK; kt++) {
        int s = kt % NSTAGE;
        cpa_wait();
        __syncthreads();
        compute_tile(f, s, c);
        __syncthreads();
        if (kt + NSTAGE < NK) {
            uint32_t ab = sb + s * STAGE_BYTES, bb = ab + TILE_BYTES;
#pragma unroll
            for (int i = 0; i < 4; i++) {
                cpa16(ab + dsto[i], asrc[i], 16);
                cpa16(bb + dsto[i], bsrc[i], 16);
                asrc[i] += BKF; bsrc[i] += BKF;
            }
        }
        cpa_commit();
    }

    // epilogue: scale + atomic scatter
#pragma unroll
    for (int mt = 0; mt < 4; mt++) {
        int ml0 = f.wm + mt * 16 + f.g;
        int ml1 = ml0 + 8;
        int tok0 = stok[ml0], tok1 = stok[ml1];
        float w0 = swv[ml0], w1v = swv[ml1];
#pragma unroll
        for (int nt = 0; nt < 4; nt++) {
            int nb = n0 + f.wn + nt * 8 + f.tg * 2;
            if (tok0 >= 0) {
                atomicAdd(out + (size_t)tok0 * DIM + nb,     c[mt][nt][0] * w0);
                atomicAdd(out + (size_t)tok0 * DIM + nb + 1, c[mt][nt][1] * w0);
            }
            if (tok1 >= 0) {
                atomicAdd(out + (size_t)tok1 * DIM + nb,     c[mt][nt][2] * w1v);
                atomicAdd(out + (size_t)tok1 * DIM + nb + 1, c[mt][nt][3] * w1v);
            }
        }
    }
}

// ---------------- launcher ----------------
extern "C" void kernel_launch(void* const* d_in, const int* in_sizes, int n_in,
                              void* d_out, int out_size) {
    const float* x  = (const float*)d_in[0];
    const float* rw = (const float*)d_in[1];
    const float* w1 = (const float*)d_in[2];
    const float* w2 = (const float*)d_in[3];
    float* out = (float*)d_out;

    static int configured = 0;
    if (!configured) {
        cudaFuncSetAttribute(gemm1_p, cudaFuncAttributeMaxDynamicSharedMemorySize, SMEM_TOTAL);
        cudaFuncSetAttribute(gemm2_p, cudaFuncAttributeMaxDynamicSharedMemorySize, SMEM_TOTAL);
        configured = 1;
    }

    const int n8x  = NUM_TOK * DIM / 8;
    const int n8w1 = NEXP * FFN * DIM / 8;
    const int n8w2 = NEXP * DIM * FFN / 8;

    init_kernel<<<(out_size + 255) / 256, 256>>>(out, out_size);
    f2h_kernel<<<(n8x  + 255) / 256, 256>>>((const float4*)x,  0, n8x);
    f2h_kernel<<<(n8w1 + 255) / 256, 256>>>((const float4*)w1, 1, n8w1);
    f2h_kernel<<<(n8w2 + 255) / 256, 256>>>((const float4*)w2, 2, n8w2);
    router_kernel<<<NUM_TOK / 8, 256>>>(x, rw);
    offsets_kernel<<<1, 256>>>();
    place_kernel<<<NUM_TOK / 256, 256>>>();
    gemm1_p<<<dim3(MAX_MTILES, FFN / BN), 256, SMEM_TOTAL>>>();
    gemm2_p<<<dim3(MAX_MTILES, DIM / BN), 256, SMEM_TOTAL>>>(out);
}

// round 7
// speedup vs baseline: 3.6162x; 1.0113x over previous
#include <cuda_runtime.h>
#include <cuda_fp16.h>
#include <cstdint>
#include <math.h>

// Problem constants
#define NUM_TOK 8192
#define DIM     1024
#define NEXP    8
#define FFN     4096

// GEMM tiling (fp16): 128x128 tiles, K-tile = 64 halves = 128 B/row
#define BM 128
#define BN 128
#define BKF 64
#define NSTAGE 3
#define MAX_SLOTS (2*NUM_TOK + NEXP*BM)     // 17408
#define MAX_MTILES (MAX_SLOTS/BM)           // 136

#define TILE_BYTES 16384                    // 128 rows x 128 B
#define STAGE_BYTES (2*TILE_BYTES)
#define SMEM_TOTAL (NSTAGE*STAGE_BYTES + 128)

// ---------------- device scratch ----------------
__device__ int    g_counts[NEXP];
__device__ int    g_fill[NEXP];
__device__ int    g_off[NEXP+1];
__device__ int    g_flag;
__device__ int    g_tok_e[2*NUM_TOK];
__device__ float  g_tok_w[2*NUM_TOK];
__device__ int    g_slot_tok[MAX_SLOTS];
__device__ float  g_slot_w[MAX_SLOTS];
__device__ __half g_xh[(size_t)NUM_TOK * DIM];
__device__ __half g_w1h[(size_t)NEXP * FFN * DIM];
__device__ __half g_w2h[(size_t)NEXP * DIM * FFN];
__device__ __half g_hh[(size_t)MAX_SLOTS * FFN];

// ---------------- helpers ----------------
__device__ __forceinline__ float gelu_exact(float v) {
    return 0.5f * v * (1.0f + erff(v * 0.70710678118654752f));
}
__device__ __forceinline__ uint32_t smem_u32(const void* p) {
    uint32_t a;
    asm("{ .reg .u64 t; cvta.to.shared.u64 t, %1; cvt.u32.u64 %0, t; }" : "=r"(a) : "l"(p));
    return a;
}
__device__ __forceinline__ void mma_f16(float c[4], const uint32_t a[4], const uint32_t b[2]) {
    asm volatile(
        "mma.sync.aligned.m16n8k16.row.col.f32.f16.f16.f32 "
        "{%0,%1,%2,%3},{%4,%5,%6,%7},{%8,%9},{%0,%1,%2,%3};"
        : "+f"(c[0]), "+f"(c[1]), "+f"(c[2]), "+f"(c[3])
        : "r"(a[0]), "r"(a[1]), "r"(a[2]), "r"(a[3]), "r"(b[0]), "r"(b[1]));
}
__device__ __forceinline__ void ldsm4(uint32_t& r0, uint32_t& r1, uint32_t& r2, uint32_t& r3,
                                      uint32_t addr) {
    asm volatile("ldmatrix.sync.aligned.m8n8.x4.shared.b16 {%0,%1,%2,%3}, [%4];"
                 : "=r"(r0), "=r"(r1), "=r"(r2), "=r"(r3) : "r"(addr));
}
__device__ __forceinline__ void cpa16(uint32_t dst, const void* src, int srcbytes) {
    asm volatile("cp.async.cg.shared.global [%0], [%1], 16, %2;"
                 :: "r"(dst), "l"(src), "r"(srcbytes) : "memory");
}
__device__ __forceinline__ void cpa_commit() { asm volatile("cp.async.commit_group;" ::: "memory"); }
__device__ __forceinline__ void cpa_wait1()  { asm volatile("cp.async.wait_group 1;" ::: "memory"); }

// ---------------- prep: reset counters + fp32->fp16 of x, w1, w2 ----------------
__global__ void prep_kernel(const float4* __restrict__ x, const float4* __restrict__ w1,
                            const float4* __restrict__ w2) {
    const int n8x  = NUM_TOK * DIM / 8;
    const int n8w1 = NEXP * FFN * DIM / 8;
    int i = blockIdx.x * blockDim.x + threadIdx.x;
    if (i < NEXP) { g_counts[i] = 0; g_fill[i] = 0; }
    if (i == NEXP) g_flag = 0;

    const float4* src;
    __half* dst;
    int j = i;
    if (j < n8x) { src = x; dst = g_xh; }
    else if (j < n8x + n8w1) { j -= n8x; src = w1; dst = g_w1h; }
    else { j -= n8x + n8w1; src = w2; dst = g_w2h; }

    float4 v0 = src[2 * j], v1 = src[2 * j + 1];
    __half2 h0 = __floats2half2_rn(v0.x, v0.y);
    __half2 h1 = __floats2half2_rn(v0.z, v0.w);
    __half2 h2 = __floats2half2_rn(v1.x, v1.y);
    __half2 h3 = __floats2half2_rn(v1.z, v1.w);
    uint4 o;
    o.x = *(uint32_t*)&h0; o.y = *(uint32_t*)&h1;
    o.z = *(uint32_t*)&h2; o.w = *(uint32_t*)&h3;
    ((uint4*)dst)[j] = o;
}

__global__ void zero_out_kernel(float4* __restrict__ out, int n4) {
    int i = blockIdx.x * blockDim.x + threadIdx.x;
    if (i < n4) out[i] = make_float4(0.f, 0.f, 0.f, 0.f);
}

// ---------------- router ----------------
__global__ void router_kernel(const float* __restrict__ x, const float* __restrict__ rw) {
    int warp = threadIdx.x >> 5, lane = threadIdx.x & 31;
    int t = blockIdx.x * 8 + warp;
    float acc[NEXP];
#pragma unroll
    for (int e = 0; e < NEXP; e++) acc[e] = 0.0f;
    const float* xp = x + (size_t)t * DIM;
    for (int k = lane; k < DIM; k += 32) {
        float xv = xp[k];
#pragma unroll
        for (int e = 0; e < NEXP; e++) acc[e] += xv * rw[e * DIM + k];
    }
#pragma unroll
    for (int e = 0; e < NEXP; e++) {
#pragma unroll
        for (int o = 16; o > 0; o >>= 1) acc[e] += __shfl_xor_sync(0xffffffffu, acc[e], o);
    }
    if (lane == 0) {
        int be = 0; float bv = acc[0];
#pragma unroll
        for (int e = 1; e < NEXP; e++) if (acc[e] > bv) { bv = acc[e]; be = e; }
        int be2 = -1; float bv2 = -1e30f;
#pragma unroll
        for (int e = 0; e < NEXP; e++) if (e != be && acc[e] > bv2) { bv2 = acc[e]; be2 = e; }
        float p0 = 1.0f / (1.0f + expf(bv2 - bv));
        g_tok_e[2 * t] = be;  g_tok_e[2 * t + 1] = be2;
        g_tok_w[2 * t] = p0;  g_tok_w[2 * t + 1] = 1.0f - p0;
        atomicAdd(&g_counts[be], 1);
        atomicAdd(&g_counts[be2], 1);
    }
}

// ---------------- place (offsets fused via device-flag spin; 32 resident blocks) ----------------
__global__ void place_kernel() {
    int flat = blockIdx.x * blockDim.x + threadIdx.x;
    if (flat == 0) {
        int o = 0;
        for (int e = 0; e < NEXP; e++) {
            g_off[e] = o;
            o += ((g_counts[e] + BM - 1) / BM) * BM;
        }
        g_off[NEXP] = o;
        __threadfence();
        atomicExch(&g_flag, 1);
    }
    while (atomicAdd(&g_flag, 0) == 0) {}
    __threadfence();

    // padding slots
    if (flat < NEXP * BM) {
        int e = flat / BM, j = flat % BM;
        int idx = g_off[e] + g_counts[e] + j;
        if (idx < g_off[e + 1]) { g_slot_tok[idx] = -1; g_slot_w[idx] = 0.0f; }
    }
    // token placement
    int t = flat;
    if (t < NUM_TOK) {
#pragma unroll
        for (int k = 0; k < 2; k++) {
            int e = g_tok_e[2 * t + k];
            int p = atomicAdd(&g_fill[e], 1);
            int idx = g_off[e] + p;
            g_slot_tok[idx] = t;
            g_slot_w[idx] = g_tok_w[2 * t + k];
        }
    }
}

// ================= fp16 pipelined GEMM core (single-barrier multistage) =================
struct Frag {
    uint32_t aB, bB;
    int wm, wn;
    int rlA, selA, rlA7;
    int nlB, selB, nlB7;
    int g, tg;
};

__device__ __forceinline__ void frag_init(Frag& f, uint32_t sb, int tid) {
    f.aB = sb; f.bB = sb + TILE_BYTES;
    int warp = tid >> 5, lane = tid & 31;
    f.wm = (warp >> 2) * 64; f.wn = (warp & 3) * 32;
    f.rlA = lane & 15;  f.selA = lane >> 4;        f.rlA7 = f.rlA & 7;
    f.nlB = ((lane >> 4) << 3) + (lane & 7);
    f.selB = (lane >> 3) & 1;                      f.nlB7 = f.nlB & 7;
    f.g = lane >> 2; f.tg = lane & 3;
}

__device__ __forceinline__ void compute_tile(const Frag& f, int s, float c[4][4][4]) {
    uint32_t aS = f.aB + s * STAGE_BYTES;
    uint32_t bS = f.bB + s * STAGE_BYTES;
#pragma unroll
    for (int ks = 0; ks < 4; ks++) {
        uint32_t a[4][4], b[4][2];
        uint32_t offA = ((uint32_t)((ks * 2 + f.selA) ^ f.rlA7)) << 4;
#pragma unroll
        for (int mt = 0; mt < 4; mt++) {
            uint32_t ad = aS + (uint32_t)(f.wm + mt * 16 + f.rlA) * 128 + offA;
            ldsm4(a[mt][0], a[mt][1], a[mt][2], a[mt][3], ad);
        }
        uint32_t offB = ((uint32_t)((ks * 2 + f.selB) ^ f.nlB7)) << 4;
#pragma unroll
        for (int p = 0; p < 2; p++) {
            uint32_t bd = bS + (uint32_t)(f.wn + p * 16 + f.nlB) * 128 + offB;
            ldsm4(b[2*p][0], b[2*p][1], b[2*p+1][0], b[2*p+1][1], bd);
        }
#pragma unroll
        for (int mt = 0; mt < 4; mt++)
#pragma unroll
            for (int nt = 0; nt < 4; nt++)
                mma_f16(c[mt][nt], a[mt], b[nt]);
    }
}

// ---------------- GEMM1: h = gelu(x_gather @ W1^T) ----------------
__global__ void __launch_bounds__(256, 2)
gemm1_p() {
    extern __shared__ char smem[];
    __shared__ int stok[BM];

    const int tid = threadIdx.x;
    const int m0 = blockIdx.x * BM;
    if (m0 >= g_off[NEXP]) return;
    int e = 0;
    while (m0 >= g_off[e + 1]) e++;
    const __half* w1e = g_w1h + (size_t)e * FFN * DIM;
    const int n0 = blockIdx.y * BN;

    if (tid < BM) stok[tid] = g_slot_tok[m0 + tid];
    __syncthreads();

    uint32_t sb = (smem_u32(smem) + 127u) & ~127u;

    const __half* asrc[4]; const __half* bsrc[4];
    uint32_t dsto[4]; int asz[4];
#pragma unroll
    for (int i = 0; i < 4; i++) {
        int idx = tid + i * 256;
        int row = idx >> 3, ch = idx & 7;
        int tok = stok[row];
        asz[i]  = (tok < 0) ? 0 : 16;
        asrc[i] = g_xh + (size_t)((tok < 0) ? 0 : tok) * DIM + ch * 8;
        bsrc[i] = w1e + (size_t)(n0 + row) * DIM + ch * 8;
        dsto[i] = (uint32_t)row * 128 + ((uint32_t)(ch ^ (row & 7)) << 4);
    }

    Frag f; frag_init(f, sb, tid);

    float c[4][4][4];
#pragma unroll
    for (int i = 0; i < 4; i++)
#pragma unroll
        for (int j = 0; j < 4; j++)
#pragma unroll
            for (int k = 0; k < 4; k++) c[i][j][k] = 0.0f;

    const int NK = DIM / BKF;   // 16
    // prologue: 2 stages only (single-barrier discipline)
#pragma unroll
    for (int s = 0; s < 2; s++) {
        uint32_t ab = sb + s * STAGE_BYTES, bb = ab + TILE_BYTES;
#pragma unroll
        for (int i = 0; i < 4; i++) {
            cpa16(ab + dsto[i], asrc[i], asz[i]);
            cpa16(bb + dsto[i], bsrc[i], 16);
            asrc[i] += BKF; bsrc[i] += BKF;
        }
        cpa_commit();
    }

    for (int kt = 0; kt < NK; kt++) {
        int s = kt % NSTAGE;
        cpa_wait1();
        __syncthreads();
        compute_tile(f, s, c);
        // issue stage kt+2 into slot (kt+2)%3 == (kt-1)%3: consumed at kt-1,
        // ordered by this iteration's top barrier.
        if (kt + 2 < NK) {
            int sn = (kt + 2) % NSTAGE;
            uint32_t ab = sb + sn * STAGE_BYTES, bb = ab + TILE_BYTES;
#pragma unroll
            for (int i = 0; i < 4; i++) {
                cpa16(ab + dsto[i], asrc[i], asz[i]);
                cpa16(bb + dsto[i], bsrc[i], 16);
                asrc[i] += BKF; bsrc[i] += BKF;
            }
        }
        cpa_commit();
    }

    // epilogue: gelu -> fp16 h
#pragma unroll
    for (int mt = 0; mt < 4; mt++) {
#pragma unroll
        for (int nt = 0; nt < 4; nt++) {
            int mb = m0 + f.wm + mt * 16 + f.g;
            int nb = n0 + f.wn + nt * 8 + f.tg * 2;
            __half2 v0 = __floats2half2_rn(gelu_exact(c[mt][nt][0]), gelu_exact(c[mt][nt][1]));
            __half2 v1 = __floats2half2_rn(gelu_exact(c[mt][nt][2]), gelu_exact(c[mt][nt][3]));
            *(__half2*)(g_hh + (size_t)mb * FFN + nb) = v0;
            *(__half2*)(g_hh + (size_t)(mb + 8) * FFN + nb) = v1;
        }
    }
}

// ---------------- GEMM2: out += w_slot * (h @ W2^T) ----------------
__global__ void __launch_bounds__(256, 2)
gemm2_p(float* __restrict__ out) {
    extern __shared__ char smem[];
    __shared__ int   stok[BM];
    __shared__ float swv[BM];

    const int tid = threadIdx.x;
    const int m0 = blockIdx.x * BM;
    if (m0 >= g_off[NEXP]) return;
    int e = 0;
    while (m0 >= g_off[e + 1]) e++;
    const __half* w2e = g_w2h + (size_t)e * DIM * FFN;
    const int n0 = blockIdx.y * BN;

    if (tid < BM) { stok[tid] = g_slot_tok[m0 + tid]; swv[tid] = g_slot_w[m0 + tid]; }
    __syncthreads();

    uint32_t sb = (smem_u32(smem) + 127u) & ~127u;

    const __half* asrc[4]; const __half* bsrc[4];
    uint32_t dsto[4];
#pragma unroll
    for (int i = 0; i < 4; i++) {
        int idx = tid + i * 256;
        int row = idx >> 3, ch = idx & 7;
        asrc[i] = g_hh + (size_t)(m0 + row) * FFN + ch * 8;
        bsrc[i] = w2e + (size_t)(n0 + row) * FFN + ch * 8;
        dsto[i] = (uint32_t)row * 128 + ((uint32_t)(ch ^ (row & 7)) << 4);
    }

    Frag f; frag_init(f, sb, tid);

    float c[4][4][4];
#pragma unroll
    for (int i = 0; i < 4; i++)
#pragma unroll
        for (int j = 0; j < 4; j++)
#pragma unroll
            for (int k = 0; k < 4; k++) c[i][j][k] = 0.0f;

    const int NK = FFN / BKF;   // 64
#pragma unroll
    for (int s = 0; s < 2; s++) {
        uint32_t ab = sb + s * STAGE_BYTES, bb = ab + TILE_BYTES;
#pragma unroll
        for (int i = 0; i < 4; i++) {
            cpa16(ab + dsto[i], asrc[i], 16);
            cpa16(bb + dsto[i], bsrc[i], 16);
            asrc[i] += BKF; bsrc[i] += BKF;
        }
        cpa_commit();
    }

    for (int kt = 0; kt < NK; kt++) {
        int s = kt % NSTAGE;
        cpa_wait1();
        __syncthreads();
        compute_tile(f, s, c);
        if (kt + 2 < NK) {
            int sn = (kt + 2) % NSTAGE;
            uint32_t ab = sb + sn * STAGE_BYTES, bb = ab + TILE_BYTES;
#pragma unroll
            for (int i = 0; i < 4; i++) {
                cpa16(ab + dsto[i], asrc[i], 16);
                cpa16(bb + dsto[i], bsrc[i], 16);
                asrc[i] += BKF; bsrc[i] += BKF;
            }
        }
        cpa_commit();
    }

    // epilogue: scale + atomic scatter
#pragma unroll
    for (int mt = 0; mt < 4; mt++) {
        int ml0 = f.wm + mt * 16 + f.g;
        int ml1 = ml0 + 8;
        int tok0 = stok[ml0], tok1 = stok[ml1];
        float w0 = swv[ml0], w1v = swv[ml1];
#pragma unroll
        for (int nt = 0; nt < 4; nt++) {
            int nb = n0 + f.wn + nt * 8 + f.tg * 2;
            if (tok0 >= 0) {
                atomicAdd(out + (size_t)tok0 * DIM + nb,     c[mt][nt][0] * w0);
                atomicAdd(out + (size_t)tok0 * DIM + nb + 1, c[mt][nt][1] * w0);
            }
            if (tok1 >= 0) {
                atomicAdd(out + (size_t)tok1 * DIM + nb,     c[mt][nt][2] * w1v);
                atomicAdd(out + (size_t)tok1 * DIM + nb + 1, c[mt][nt][3] * w1v);
            }
        }
    }
}

// ---------------- launcher ----------------
extern "C" void kernel_launch(void* const* d_in, const int* in_sizes, int n_in,
                              void* d_out, int out_size) {
    const float* x  = (const float*)d_in[0];
    const float* rw = (const float*)d_in[1];
    const float* w1 = (const float*)d_in[2];
    const float* w2 = (const float*)d_in[3];
    float* out = (float*)d_out;

    static int configured = 0;
    if (!configured) {
        cudaFuncSetAttribute(gemm1_p, cudaFuncAttributeMaxDynamicSharedMemorySize, SMEM_TOTAL);
        cudaFuncSetAttribute(gemm2_p, cudaFuncAttributeMaxDynamicSharedMemorySize, SMEM_TOTAL);
        configured = 1;
    }

    const int n8tot = (NUM_TOK * DIM + NEXP * FFN * DIM + NEXP * DIM * FFN) / 8;

    // launch order fixed so index 3 = gemm1, index 5 = gemm2 (profile window)
    prep_kernel<<<(n8tot + 255) / 256, 256>>>((const float4*)x, (const float4*)w1, (const float4*)w2);
    router_kernel<<<NUM_TOK / 8, 256>>>(x, rw);
    place_kernel<<<32, 256>>>();
    gemm1_p<<<dim3(MAX_MTILES, FFN / BN), 256, SMEM_TOTAL>>>();
    zero_out_kernel<<<(out_size / 4 + 255) / 256, 256>>>((float4*)out, out_size / 4);
    gemm2_p<<<dim3(MAX_MTILES, DIM / BN), 256, SMEM_TOTAL>>>(out);
}